// round 1
// baseline (speedup 1.0000x reference)
#include <cuda_runtime.h>
#include <math.h>

#define NN 100000
#define EE 1600000
#define ETOT (EE + NN)
#define NEG 0.2f
#define FULLMASK 0xffffffffu

// ---------------- scratch (device globals; no allocation allowed) ----------
__device__ float g_xl1[NN * 64];
__device__ float g_xr1[NN * 64];
__device__ float g_h1[NN * 64];
__device__ float g_xl2[NN * 40];
__device__ float g_xr2[NN * 40];
__device__ int g_cnt[NN];
__device__ int g_rowptr[NN + 1];
__device__ int g_pos[NN];
__device__ int g_esrc[ETOT];
__device__ int g_bsum[128];
__device__ int g_boff[128];

// ---------------- CSR build --------------------------------------------------
__global__ void k_zero() {
    int i = blockIdx.x * blockDim.x + threadIdx.x;
    if (i < NN) g_cnt[i] = 0;
}

__global__ void k_hist(const int* __restrict__ ei) {
    int e = blockIdx.x * blockDim.x + threadIdx.x;
    if (e >= ETOT) return;
    int dst = (e < EE) ? ei[EE + e] : (e - EE);
    atomicAdd(&g_cnt[dst], 1);
}

__global__ void k_scan1() {
    __shared__ int s[1024];
    int tid = threadIdx.x;
    int i = blockIdx.x * 1024 + tid;
    int v = (i < NN) ? g_cnt[i] : 0;
    s[tid] = v;
    __syncthreads();
    for (int off = 1; off < 1024; off <<= 1) {
        int t = (tid >= off) ? s[tid - off] : 0;
        __syncthreads();
        s[tid] += t;
        __syncthreads();
    }
    if (i < NN) g_rowptr[i + 1] = s[tid];
    if (tid == 1023) g_bsum[blockIdx.x] = s[1023];
}

__global__ void k_scan2(int nb) {
    if (threadIdx.x == 0) {
        int run = 0;
        for (int b = 0; b < nb; b++) { g_boff[b] = run; run += g_bsum[b]; }
    }
}

__global__ void k_scan3() {
    int tid = threadIdx.x;
    int i = blockIdx.x * 1024 + tid;
    if (i < NN) {
        int rp = g_rowptr[i + 1] + g_boff[blockIdx.x];
        g_rowptr[i + 1] = rp;
        g_pos[i] = rp - g_cnt[i];
        if (i == 0) g_rowptr[0] = 0;
    }
}

__global__ void k_scatter(const int* __restrict__ ei) {
    int e = blockIdx.x * blockDim.x + threadIdx.x;
    if (e >= ETOT) return;
    int src, dst;
    if (e < EE) { src = ei[e]; dst = ei[EE + e]; }
    else        { src = dst = e - EE; }
    int p = atomicAdd(&g_pos[dst], 1);
    g_esrc[p] = src;
}

// ---------------- GEMM1: x[N,256] @ W[256,64] (+bias) twice (Wl, Wr) --------
// Tile 128x64, K-chunk 16, 256 threads, thread tile 8x4.
__global__ __launch_bounds__(256) void k_gemm1(
    const float* __restrict__ A,
    const float* __restrict__ Wl, const float* __restrict__ bl,
    const float* __restrict__ Wr, const float* __restrict__ br) {
    const float* W = blockIdx.y ? Wr : Wl;
    const float* bias = blockIdx.y ? br : bl;
    float* C = blockIdx.y ? g_xr1 : g_xl1;

    __shared__ float As[16][132];  // [k][m], padded (132*4 = 16B multiple)
    __shared__ float Bs[16][68];   // [k][n], padded (68*4 = 16B multiple)

    int tid = threadIdx.x;
    int m0 = blockIdx.x * 128;
    int tx = tid & 15, ty = tid >> 4;

    float acc[8][4];
#pragma unroll
    for (int i = 0; i < 8; i++)
#pragma unroll
        for (int j = 0; j < 4; j++) acc[i][j] = 0.0f;

    int lrow = tid >> 1, lk = (tid & 1) * 8;
    int brow = tid >> 4, bc = (tid & 15) * 4;
    int grow = m0 + lrow;

    for (int k0 = 0; k0 < 256; k0 += 16) {
        float4 a0, a1;
        if (grow < NN) {
            a0 = *(const float4*)(A + grow * 256 + k0 + lk);
            a1 = *(const float4*)(A + grow * 256 + k0 + lk + 4);
        } else {
            a0 = make_float4(0.f, 0.f, 0.f, 0.f);
            a1 = a0;
        }
        float4 b0 = *(const float4*)(W + (k0 + brow) * 64 + bc);
        __syncthreads();
        As[lk + 0][lrow] = a0.x; As[lk + 1][lrow] = a0.y;
        As[lk + 2][lrow] = a0.z; As[lk + 3][lrow] = a0.w;
        As[lk + 4][lrow] = a1.x; As[lk + 5][lrow] = a1.y;
        As[lk + 6][lrow] = a1.z; As[lk + 7][lrow] = a1.w;
        *(float4*)&Bs[brow][bc] = b0;
        __syncthreads();
#pragma unroll
        for (int k = 0; k < 16; k++) {
            float4 av0 = *(const float4*)&As[k][ty * 8];
            float4 av1 = *(const float4*)&As[k][ty * 8 + 4];
            float4 bv  = *(const float4*)&Bs[k][tx * 4];
            float a[8] = {av0.x, av0.y, av0.z, av0.w, av1.x, av1.y, av1.z, av1.w};
            float b[4] = {bv.x, bv.y, bv.z, bv.w};
#pragma unroll
            for (int i = 0; i < 8; i++)
#pragma unroll
                for (int j = 0; j < 4; j++) acc[i][j] += a[i] * b[j];
        }
    }

    float bb[4];
#pragma unroll
    for (int j = 0; j < 4; j++) bb[j] = bias[tx * 4 + j];
#pragma unroll
    for (int i = 0; i < 8; i++) {
        int row = m0 + ty * 8 + i;
        if (row < NN) {
#pragma unroll
            for (int j = 0; j < 4; j++)
                C[row * 64 + tx * 4 + j] = acc[i][j] + bb[j];
        }
    }
}

// ---------------- Aggregation layer 1: warp per dst node, 8 heads x 8 ch ----
__global__ __launch_bounds__(256) void k_agg1(const float* __restrict__ att,
                                              const float* __restrict__ bias) {
    int gt = blockIdx.x * blockDim.x + threadIdx.x;
    int n = gt >> 5;
    int lane = gt & 31;
    if (n >= NN) return;

    const float2* xl = (const float2*)g_xl1;
    float2 xr = ((const float2*)g_xr1)[n * 32 + lane];
    float a0 = att[lane * 2], a1 = att[lane * 2 + 1];
    int beg = g_rowptr[n], end = g_rowptr[n + 1];

    float mx = -1e30f;
    for (int j = beg; j < end; j++) {
        int s = g_esrc[j];
        float2 v = xl[s * 32 + lane];
        float m0 = v.x + xr.x, m1 = v.y + xr.y;
        m0 = m0 > 0.f ? m0 : NEG * m0;
        m1 = m1 > 0.f ? m1 : NEG * m1;
        float p = m0 * a0 + m1 * a1;
        p += __shfl_xor_sync(FULLMASK, p, 1);
        p += __shfl_xor_sync(FULLMASK, p, 2);
        mx = fmaxf(mx, p);
    }

    float acc0 = 0.f, acc1 = 0.f, ssum = 0.f;
    for (int j = beg; j < end; j++) {
        int s = g_esrc[j];
        float2 v = xl[s * 32 + lane];
        float m0 = v.x + xr.x, m1 = v.y + xr.y;
        m0 = m0 > 0.f ? m0 : NEG * m0;
        m1 = m1 > 0.f ? m1 : NEG * m1;
        float p = m0 * a0 + m1 * a1;
        p += __shfl_xor_sync(FULLMASK, p, 1);
        p += __shfl_xor_sync(FULLMASK, p, 2);
        float e = __expf(p - mx);
        ssum += e;
        acc0 += e * v.x;
        acc1 += e * v.y;
    }
    float inv = 1.0f / ssum;
    float o0 = acc0 * inv + bias[lane * 2];
    float o1 = acc1 * inv + bias[lane * 2 + 1];
    o0 = o0 > 0.f ? o0 : expm1f(o0);   // ELU(alpha=1)
    o1 = o1 > 0.f ? o1 : expm1f(o1);
    ((float2*)g_h1)[n * 32 + lane] = make_float2(o0, o1);
}

// ---------------- GEMM2: h1[N,64] @ {Wl2,Wr2}[64,40] -----------------------
// Tile 64 rows x 80 cols (Wl|Wr fused), 256 threads, thread tile 4x5.
__global__ __launch_bounds__(256) void k_gemm2(
    const float* __restrict__ Wl, const float* __restrict__ bl,
    const float* __restrict__ Wr, const float* __restrict__ br) {
    __shared__ float Hst[64][65];  // [k][row]
    __shared__ float Ws[64][80];   // cols 0-39 = Wl, 40-79 = Wr
    int tid = threadIdx.x;
    int m0 = blockIdx.x * 64;

    {
        int r = tid >> 2, c0 = (tid & 3) * 16;
        int row = m0 + r;
#pragma unroll
        for (int j = 0; j < 16; j += 4) {
            float4 v = (row < NN) ? *(const float4*)&g_h1[row * 64 + c0 + j]
                                  : make_float4(0.f, 0.f, 0.f, 0.f);
            Hst[c0 + j + 0][r] = v.x;
            Hst[c0 + j + 1][r] = v.y;
            Hst[c0 + j + 2][r] = v.z;
            Hst[c0 + j + 3][r] = v.w;
        }
    }
    for (int i = tid; i < 2560; i += 256) {
        int k = i / 40, c = i % 40;
        Ws[k][c] = Wl[i];
        Ws[k][c + 40] = Wr[i];
    }
    __syncthreads();

    int rg = tid >> 4, cg = tid & 15;
    float acc[4][5];
#pragma unroll
    for (int i = 0; i < 4; i++)
#pragma unroll
        for (int j = 0; j < 5; j++) acc[i][j] = 0.0f;

#pragma unroll 4
    for (int k = 0; k < 64; k++) {
        float a[4], w[5];
#pragma unroll
        for (int i = 0; i < 4; i++) a[i] = Hst[k][rg * 4 + i];
#pragma unroll
        for (int j = 0; j < 5; j++) w[j] = Ws[k][cg * 5 + j];
#pragma unroll
        for (int i = 0; i < 4; i++)
#pragma unroll
            for (int j = 0; j < 5; j++) acc[i][j] += a[i] * w[j];
    }

#pragma unroll
    for (int i = 0; i < 4; i++) {
        int row = m0 + rg * 4 + i;
        if (row < NN) {
#pragma unroll
            for (int j = 0; j < 5; j++) {
                int c = cg * 5 + j;
                if (c < 40) g_xl2[row * 40 + c] = acc[i][j] + bl[c];
                else        g_xr2[row * 40 + c - 40] = acc[i][j] + br[c - 40];
            }
        }
    }
}

// ---------------- Aggregation layer 2 + log_softmax: warp per node ----------
__global__ __launch_bounds__(256) void k_agg2(const float* __restrict__ att,
                                              const float* __restrict__ bias,
                                              float* __restrict__ out) {
    int gt = blockIdx.x * blockDim.x + threadIdx.x;
    int n = gt >> 5;
    int lane = gt & 31;
    if (n >= NN) return;

    bool hi = lane < 8;
    float xr0 = g_xr2[n * 40 + lane];
    float xr1 = hi ? g_xr2[n * 40 + 32 + lane] : 0.0f;
    float a0 = att[lane];
    float a1 = hi ? att[32 + lane] : 0.0f;
    int beg = g_rowptr[n], end = g_rowptr[n + 1];

    float mx = -1e30f;
    for (int j = beg; j < end; j++) {
        int s = g_esrc[j];
        float v0 = g_xl2[s * 40 + lane];
        float v1 = hi ? g_xl2[s * 40 + 32 + lane] : 0.0f;
        float m0 = v0 + xr0, m1 = v1 + xr1;
        m0 = m0 > 0.f ? m0 : NEG * m0;
        m1 = m1 > 0.f ? m1 : NEG * m1;
        float p = m0 * a0 + m1 * a1;
#pragma unroll
        for (int off = 16; off; off >>= 1) p += __shfl_xor_sync(FULLMASK, p, off);
        mx = fmaxf(mx, p);
    }

    float acc0 = 0.f, acc1 = 0.f, ssum = 0.f;
    for (int j = beg; j < end; j++) {
        int s = g_esrc[j];
        float v0 = g_xl2[s * 40 + lane];
        float v1 = hi ? g_xl2[s * 40 + 32 + lane] : 0.0f;
        float m0 = v0 + xr0, m1 = v1 + xr1;
        m0 = m0 > 0.f ? m0 : NEG * m0;
        m1 = m1 > 0.f ? m1 : NEG * m1;
        float p = m0 * a0 + m1 * a1;
#pragma unroll
        for (int off = 16; off; off >>= 1) p += __shfl_xor_sync(FULLMASK, p, off);
        float e = __expf(p - mx);
        ssum += e;
        acc0 += e * v0;
        acc1 += e * v1;
    }
    float inv = 1.0f / ssum;
    float o0 = acc0 * inv + bias[lane];
    float o1 = hi ? (acc1 * inv + bias[32 + lane]) : -1e30f;

    // fused log_softmax over 40 logits
    float vm = fmaxf(o0, o1);
#pragma unroll
    for (int off = 16; off; off >>= 1) vm = fmaxf(vm, __shfl_xor_sync(FULLMASK, vm, off));
    float es = __expf(o0 - vm) + (hi ? __expf(o1 - vm) : 0.0f);
#pragma unroll
    for (int off = 16; off; off >>= 1) es += __shfl_xor_sync(FULLMASK, es, off);
    float ls = vm + logf(es);
    out[n * 40 + lane] = o0 - ls;
    if (hi) out[n * 40 + 32 + lane] = o1 - ls;
}

// ---------------- launch -----------------------------------------------------
extern "C" void kernel_launch(void* const* d_in, const int* in_sizes, int n_in,
                              void* d_out, int out_size) {
    const float* x    = (const float*)d_in[0];
    const int*   ei   = (const int*)d_in[1];
    const float* Wl1  = (const float*)d_in[2];
    const float* bl1  = (const float*)d_in[3];
    const float* Wr1  = (const float*)d_in[4];
    const float* br1  = (const float*)d_in[5];
    const float* att1 = (const float*)d_in[6];
    const float* bias1= (const float*)d_in[7];
    const float* Wl2  = (const float*)d_in[8];
    const float* bl2  = (const float*)d_in[9];
    const float* Wr2  = (const float*)d_in[10];
    const float* br2  = (const float*)d_in[11];
    const float* att2 = (const float*)d_in[12];
    const float* bias2= (const float*)d_in[13];
    float* out = (float*)d_out;

    int nb = (NN + 1023) / 1024;

    k_zero<<<(NN + 255) / 256, 256>>>();
    k_hist<<<(ETOT + 255) / 256, 256>>>(ei);
    k_scan1<<<nb, 1024>>>();
    k_scan2<<<1, 32>>>(nb);
    k_scan3<<<nb, 1024>>>();
    k_scatter<<<(ETOT + 255) / 256, 256>>>(ei);

    k_gemm1<<<dim3((NN + 127) / 128, 2), 256>>>(x, Wl1, bl1, Wr1, br1);
    k_agg1<<<(NN * 32) / 256, 256>>>(att1, bias1);
    k_gemm2<<<(NN + 63) / 64, 256>>>(Wl2, bl2, Wr2, br2);
    k_agg2<<<(NN * 32) / 256, 256>>>(att2, bias2, out);
}

// round 2
// speedup vs baseline: 1.1998x; 1.1998x over previous
#include <cuda_runtime.h>
#include <math.h>

#define NN 100000
#define EE 1600000
#define ETOT (EE + NN)
#define NEG 0.2f
#define FULLMASK 0xffffffffu

// ---------------- scratch (device globals; no allocation allowed) ----------
__device__ float g_xl1[NN * 64];
__device__ float g_xr1[NN * 64];
__device__ float g_h1[NN * 64];
__device__ float g_xl2[NN * 40];
__device__ float g_xr2[NN * 40];
__device__ int g_cnt[NN];
__device__ int g_rowptr[NN + 1];
__device__ int g_pos[NN];
__device__ int g_esrc[ETOT];
__device__ int g_bsum[128];
__device__ int g_boff[128];

// ---------------- CSR build --------------------------------------------------
__global__ void k_zero() {
    int i = blockIdx.x * blockDim.x + threadIdx.x;
    if (i < NN) g_cnt[i] = 0;
}

__global__ void k_hist(const int* __restrict__ ei) {
    int e = blockIdx.x * blockDim.x + threadIdx.x;
    if (e >= ETOT) return;
    int dst = (e < EE) ? ei[EE + e] : (e - EE);
    atomicAdd(&g_cnt[dst], 1);
}

__global__ void k_scan1() {
    __shared__ int s[1024];
    int tid = threadIdx.x;
    int i = blockIdx.x * 1024 + tid;
    int v = (i < NN) ? g_cnt[i] : 0;
    s[tid] = v;
    __syncthreads();
    for (int off = 1; off < 1024; off <<= 1) {
        int t = (tid >= off) ? s[tid - off] : 0;
        __syncthreads();
        s[tid] += t;
        __syncthreads();
    }
    if (i < NN) g_rowptr[i + 1] = s[tid];
    if (tid == 1023) g_bsum[blockIdx.x] = s[1023];
}

// parallel exclusive scan of up to 128 block sums (1 block, 128 threads)
__global__ void k_scan2(int nb) {
    __shared__ int s[128];
    int tid = threadIdx.x;
    int v = (tid < nb) ? g_bsum[tid] : 0;
    s[tid] = v;
    __syncthreads();
    for (int off = 1; off < 128; off <<= 1) {
        int t = (tid >= off) ? s[tid - off] : 0;
        __syncthreads();
        s[tid] += t;
        __syncthreads();
    }
    if (tid < nb) g_boff[tid] = s[tid] - v;  // exclusive
}

__global__ void k_scan3() {
    int tid = threadIdx.x;
    int i = blockIdx.x * 1024 + tid;
    if (i < NN) {
        int rp = g_rowptr[i + 1] + g_boff[blockIdx.x];
        g_rowptr[i + 1] = rp;
        g_pos[i] = rp - g_cnt[i];
        if (i == 0) g_rowptr[0] = 0;
    }
}

__global__ void k_scatter(const int* __restrict__ ei) {
    int e = blockIdx.x * blockDim.x + threadIdx.x;
    if (e >= ETOT) return;
    int src, dst;
    if (e < EE) { src = ei[e]; dst = ei[EE + e]; }
    else        { src = dst = e - EE; }
    int p = atomicAdd(&g_pos[dst], 1);
    g_esrc[p] = src;
}

// ---------------- GEMM1: x[N,256] @ [Wl|Wr][256,128] (+bias) fused ---------
// Tile 128x128, K-chunk 16, 256 threads, thread tile 8x8.
__global__ __launch_bounds__(256) void k_gemm1(
    const float* __restrict__ A,
    const float* __restrict__ Wl, const float* __restrict__ bl,
    const float* __restrict__ Wr, const float* __restrict__ br) {
    __shared__ float As[16][136];  // [k][m], padded
    __shared__ float Bs[16][128];  // [k][n]; n<64 = Wl, n>=64 = Wr

    int tid = threadIdx.x;
    int m0 = blockIdx.x * 128;
    int tx = tid & 15, ty = tid >> 4;  // col group, row group

    float acc[8][8];
#pragma unroll
    for (int i = 0; i < 8; i++)
#pragma unroll
        for (int j = 0; j < 8; j++) acc[i][j] = 0.0f;

    // A staging: 128 rows x 16 k = 512 float4; thread loads f = tid and tid+256
    // float4 f: row = f>>2, kcol = (f&3)*4
    // B staging: Wl: 16 rows x 64 = 256 float4 (thread tid<256 loads one);
    //            Wr: same, goes to Bs[..][64+..]
    int ar0 = tid >> 2, ak0 = (tid & 3) * 4;
    int ar1 = (tid + 256) >> 2, ak1 = ((tid + 256) & 3) * 4;
    int bk = tid >> 4, bc = (tid & 15) * 4;

    for (int k0 = 0; k0 < 256; k0 += 16) {
        float4 a0, a1;
        int gr0 = m0 + ar0, gr1 = m0 + ar1;
        a0 = (gr0 < NN) ? *(const float4*)(A + gr0 * 256 + k0 + ak0)
                        : make_float4(0.f, 0.f, 0.f, 0.f);
        a1 = (gr1 < NN) ? *(const float4*)(A + gr1 * 256 + k0 + ak1)
                        : make_float4(0.f, 0.f, 0.f, 0.f);
        float4 wl = *(const float4*)(Wl + (k0 + bk) * 64 + bc);
        float4 wr = *(const float4*)(Wr + (k0 + bk) * 64 + bc);
        __syncthreads();
        As[ak0 + 0][ar0] = a0.x; As[ak0 + 1][ar0] = a0.y;
        As[ak0 + 2][ar0] = a0.z; As[ak0 + 3][ar0] = a0.w;
        As[ak1 + 0][ar1] = a1.x; As[ak1 + 1][ar1] = a1.y;
        As[ak1 + 2][ar1] = a1.z; As[ak1 + 3][ar1] = a1.w;
        *(float4*)&Bs[bk][bc] = wl;
        *(float4*)&Bs[bk][64 + bc] = wr;
        __syncthreads();
#pragma unroll
        for (int k = 0; k < 16; k++) {
            float4 av0 = *(const float4*)&As[k][ty * 8];
            float4 av1 = *(const float4*)&As[k][ty * 8 + 4];
            float4 bv0 = *(const float4*)&Bs[k][tx * 8];
            float4 bv1 = *(const float4*)&Bs[k][tx * 8 + 4];
            float a[8] = {av0.x, av0.y, av0.z, av0.w, av1.x, av1.y, av1.z, av1.w};
            float b[8] = {bv0.x, bv0.y, bv0.z, bv0.w, bv1.x, bv1.y, bv1.z, bv1.w};
#pragma unroll
            for (int i = 0; i < 8; i++)
#pragma unroll
                for (int j = 0; j < 8; j++) acc[i][j] += a[i] * b[j];
        }
    }

    // epilogue: cols tx*8..tx*8+7 are entirely in Wl half (tx<8) or Wr half
    float bb[8];
    bool left = (tx < 8);
    int cbase = left ? tx * 8 : tx * 8 - 64;
    const float* bias = left ? bl : br;
    float* C = left ? g_xl1 : g_xr1;
#pragma unroll
    for (int j = 0; j < 8; j++) bb[j] = bias[cbase + j];
#pragma unroll
    for (int i = 0; i < 8; i++) {
        int row = m0 + ty * 8 + i;
        if (row < NN) {
            float4 o0 = make_float4(acc[i][0] + bb[0], acc[i][1] + bb[1],
                                    acc[i][2] + bb[2], acc[i][3] + bb[3]);
            float4 o1 = make_float4(acc[i][4] + bb[4], acc[i][5] + bb[5],
                                    acc[i][6] + bb[6], acc[i][7] + bb[7]);
            *(float4*)(C + row * 64 + cbase) = o0;
            *(float4*)(C + row * 64 + cbase + 4) = o1;
        }
    }
}

// ---------------- Aggregation layer 1 (single pass, no max-sub) -------------
__global__ __launch_bounds__(256) void k_agg1(const float* __restrict__ att,
                                              const float* __restrict__ bias) {
    int gt = blockIdx.x * blockDim.x + threadIdx.x;
    int n = gt >> 5;
    int lane = gt & 31;
    if (n >= NN) return;

    const float2* xl = (const float2*)g_xl1;
    float2 xr = ((const float2*)g_xr1)[n * 32 + lane];
    float a0 = att[lane * 2], a1 = att[lane * 2 + 1];
    int beg = g_rowptr[n], end = g_rowptr[n + 1];

    float acc0 = 0.f, acc1 = 0.f, ssum = 0.f;
    for (int j = beg; j < end; j++) {
        int s = g_esrc[j];
        float2 v = xl[s * 32 + lane];
        float m0 = v.x + xr.x, m1 = v.y + xr.y;
        m0 = m0 > 0.f ? m0 : NEG * m0;
        m1 = m1 > 0.f ? m1 : NEG * m1;
        float p = m0 * a0 + m1 * a1;
        p += __shfl_xor_sync(FULLMASK, p, 1);
        p += __shfl_xor_sync(FULLMASK, p, 2);
        float e = __expf(p);
        ssum += e;
        acc0 += e * v.x;
        acc1 += e * v.y;
    }
    float inv = 1.0f / ssum;
    float o0 = acc0 * inv + bias[lane * 2];
    float o1 = acc1 * inv + bias[lane * 2 + 1];
    o0 = o0 > 0.f ? o0 : expm1f(o0);   // ELU(alpha=1)
    o1 = o1 > 0.f ? o1 : expm1f(o1);
    ((float2*)g_h1)[n * 32 + lane] = make_float2(o0, o1);
}

// ---------------- GEMM2: h1[N,64] @ {Wl2,Wr2}[64,40] -----------------------
__global__ __launch_bounds__(256) void k_gemm2(
    const float* __restrict__ Wl, const float* __restrict__ bl,
    const float* __restrict__ Wr, const float* __restrict__ br) {
    __shared__ float Hst[64][65];  // [k][row]
    __shared__ float Ws[64][80];   // cols 0-39 = Wl, 40-79 = Wr
    int tid = threadIdx.x;
    int m0 = blockIdx.x * 64;

    {
        int r = tid >> 2, c0 = (tid & 3) * 16;
        int row = m0 + r;
#pragma unroll
        for (int j = 0; j < 16; j += 4) {
            float4 v = (row < NN) ? *(const float4*)&g_h1[row * 64 + c0 + j]
                                  : make_float4(0.f, 0.f, 0.f, 0.f);
            Hst[c0 + j + 0][r] = v.x;
            Hst[c0 + j + 1][r] = v.y;
            Hst[c0 + j + 2][r] = v.z;
            Hst[c0 + j + 3][r] = v.w;
        }
    }
    for (int i = tid; i < 2560; i += 256) {
        int k = i / 40, c = i % 40;
        Ws[k][c] = Wl[i];
        Ws[k][c + 40] = Wr[i];
    }
    __syncthreads();

    int rg = tid >> 4, cg = tid & 15;
    float acc[4][5];
#pragma unroll
    for (int i = 0; i < 4; i++)
#pragma unroll
        for (int j = 0; j < 5; j++) acc[i][j] = 0.0f;

#pragma unroll 4
    for (int k = 0; k < 64; k++) {
        float a[4], w[5];
#pragma unroll
        for (int i = 0; i < 4; i++) a[i] = Hst[k][rg * 4 + i];
#pragma unroll
        for (int j = 0; j < 5; j++) w[j] = Ws[k][cg * 5 + j];
#pragma unroll
        for (int i = 0; i < 4; i++)
#pragma unroll
            for (int j = 0; j < 5; j++) acc[i][j] += a[i] * w[j];
    }

#pragma unroll
    for (int i = 0; i < 4; i++) {
        int row = m0 + rg * 4 + i;
        if (row < NN) {
#pragma unroll
            for (int j = 0; j < 5; j++) {
                int c = cg * 5 + j;
                if (c < 40) g_xl2[row * 40 + c] = acc[i][j] + bl[c];
                else        g_xr2[row * 40 + c - 40] = acc[i][j] + br[c - 40];
            }
        }
    }
}

// ---------- Aggregation layer 2 (single pass) + log_softmax -----------------
__global__ __launch_bounds__(256) void k_agg2(const float* __restrict__ att,
                                              const float* __restrict__ bias,
                                              float* __restrict__ out) {
    int gt = blockIdx.x * blockDim.x + threadIdx.x;
    int n = gt >> 5;
    int lane = gt & 31;
    if (n >= NN) return;

    bool hi = lane < 8;
    float xr0 = g_xr2[n * 40 + lane];
    float xr1 = hi ? g_xr2[n * 40 + 32 + lane] : 0.0f;
    float a0 = att[lane];
    float a1 = hi ? att[32 + lane] : 0.0f;
    int beg = g_rowptr[n], end = g_rowptr[n + 1];

    float acc0 = 0.f, acc1 = 0.f, ssum = 0.f;
    for (int j = beg; j < end; j++) {
        int s = g_esrc[j];
        float v0 = g_xl2[s * 40 + lane];
        float v1 = hi ? g_xl2[s * 40 + 32 + lane] : 0.0f;
        float m0 = v0 + xr0, m1 = v1 + xr1;
        m0 = m0 > 0.f ? m0 : NEG * m0;
        m1 = m1 > 0.f ? m1 : NEG * m1;
        float p = m0 * a0 + m1 * a1;
#pragma unroll
        for (int off = 16; off; off >>= 1) p += __shfl_xor_sync(FULLMASK, p, off);
        float e = __expf(p);
        ssum += e;
        acc0 += e * v0;
        acc1 += e * v1;
    }
    float inv = 1.0f / ssum;
    float o0 = acc0 * inv + bias[lane];
    float o1 = hi ? (acc1 * inv + bias[32 + lane]) : -1e30f;

    // fused log_softmax over 40 logits
    float vm = fmaxf(o0, o1);
#pragma unroll
    for (int off = 16; off; off >>= 1) vm = fmaxf(vm, __shfl_xor_sync(FULLMASK, vm, off));
    float es = __expf(o0 - vm) + (hi ? __expf(o1 - vm) : 0.0f);
#pragma unroll
    for (int off = 16; off; off >>= 1) es += __shfl_xor_sync(FULLMASK, es, off);
    float ls = vm + logf(es);
    out[n * 40 + lane] = o0 - ls;
    if (hi) out[n * 40 + 32 + lane] = o1 - ls;
}

// ---------------- launch -----------------------------------------------------
extern "C" void kernel_launch(void* const* d_in, const int* in_sizes, int n_in,
                              void* d_out, int out_size) {
    const float* x    = (const float*)d_in[0];
    const int*   ei   = (const int*)d_in[1];
    const float* Wl1  = (const float*)d_in[2];
    const float* bl1  = (const float*)d_in[3];
    const float* Wr1  = (const float*)d_in[4];
    const float* br1  = (const float*)d_in[5];
    const float* att1 = (const float*)d_in[6];
    const float* bias1= (const float*)d_in[7];
    const float* Wl2  = (const float*)d_in[8];
    const float* bl2  = (const float*)d_in[9];
    const float* Wr2  = (const float*)d_in[10];
    const float* br2  = (const float*)d_in[11];
    const float* att2 = (const float*)d_in[12];
    const float* bias2= (const float*)d_in[13];
    float* out = (float*)d_out;

    int nb = (NN + 1023) / 1024;

    k_zero<<<(NN + 255) / 256, 256>>>();
    k_hist<<<(ETOT + 255) / 256, 256>>>(ei);
    k_scan1<<<nb, 1024>>>();
    k_scan2<<<1, 128>>>(nb);
    k_scan3<<<nb, 1024>>>();
    k_scatter<<<(ETOT + 255) / 256, 256>>>(ei);

    k_gemm1<<<(NN + 127) / 128, 256>>>(x, Wl1, bl1, Wr1, br1);
    k_agg1<<<(NN * 32) / 256, 256>>>(att1, bias1);
    k_gemm2<<<(NN + 63) / 64, 256>>>(Wl2, bl2, Wr2, br2);
    k_agg2<<<(NN * 32) / 256, 256>>>(att2, bias2, out);
}